// round 13
// baseline (speedup 1.0000x reference)
#include <cuda_runtime.h>
#include <cuda_bf16.h>
#include <cstdint>

#define SEQ 2048
#define NROWS 4096
#define HID 1024
#define GC 1536   // global proj cols: Q 0, K 512, V 1024
#define LC 2560   // local proj cols: LQ 0, LK1 512, LK2 1024, LV1 1536, LV2 2048

__device__ __nv_bfloat16 g_Xh[(size_t)NROWS * HID];
__device__ __nv_bfloat16 g_Xl[(size_t)NROWS * HID];
__device__ __nv_bfloat16 g_Wth[(size_t)4096 * HID];   // all 8 W, transposed [n][k]
__device__ __nv_bfloat16 g_Wtl[(size_t)4096 * HID];
__device__ float g_bias[4096];
__device__ __nv_bfloat16 g_Pg[(size_t)NROWS * GC];    // global projections bf16
__device__ float g_Pf[(size_t)NROWS * LC];            // local projections fp32
__device__ float g_Mpart[8 * 16 * 64 * 64];
__device__ float g_M[16 * 64 * 64];
__device__ __nv_bfloat16 g_K2h[(size_t)NROWS * 512];
__device__ __nv_bfloat16 g_K2l[(size_t)NROWS * 512];
__device__ __nv_bfloat16 g_Vmh[(size_t)NROWS * 512];
__device__ __nv_bfloat16 g_Vml[(size_t)NROWS * 512];

struct ProjArgs { const float* w[8]; const float* b[8]; };

// ---------------- helpers ----------------
__device__ __forceinline__ uint32_t cvta_s(const void* p) {
    return (uint32_t)__cvta_generic_to_shared(p);
}
__device__ __forceinline__ void cp16(void* smem, const void* gmem) {
    asm volatile("cp.async.cg.shared.global [%0], [%1], 16;"
                 :: "r"(cvta_s(smem)), "l"(gmem));
}
__device__ __forceinline__ void cp16s(uint32_t smem, const void* gmem) {
    asm volatile("cp.async.cg.shared.global [%0], [%1], 16;"
                 :: "r"(smem), "l"(gmem));
}
__device__ __forceinline__ void ldsm_x4(uint32_t r[4], uint32_t a) {
    asm volatile("ldmatrix.sync.aligned.m8n8.x4.shared.b16 {%0,%1,%2,%3}, [%4];"
                 : "=r"(r[0]), "=r"(r[1]), "=r"(r[2]), "=r"(r[3]) : "r"(a));
}
__device__ __forceinline__ void ldsm_x4t(uint32_t r[4], uint32_t a) {
    asm volatile("ldmatrix.sync.aligned.m8n8.x4.trans.shared.b16 {%0,%1,%2,%3}, [%4];"
                 : "=r"(r[0]), "=r"(r[1]), "=r"(r[2]), "=r"(r[3]) : "r"(a));
}
__device__ __forceinline__ void mma_bf16b(float c[4], const uint32_t a[4], uint32_t b0, uint32_t b1) {
    asm volatile("mma.sync.aligned.m16n8k16.row.col.f32.bf16.bf16.f32 "
                 "{%0,%1,%2,%3},{%4,%5,%6,%7},{%8,%9},{%0,%1,%2,%3};"
                 : "+f"(c[0]), "+f"(c[1]), "+f"(c[2]), "+f"(c[3])
                 : "r"(a[0]), "r"(a[1]), "r"(a[2]), "r"(a[3]), "r"(b0), "r"(b1));
}
__device__ __forceinline__ void split2(float x, __nv_bfloat16& h, __nv_bfloat16& l) {
    h = __float2bfloat16_rn(x);
    l = __float2bfloat16_rn(x - __bfloat162float(h));
}
__device__ __forceinline__ uint32_t pack_bf16(float a, float b) {
    __nv_bfloat162 t = __floats2bfloat162_rn(a, b);
    return *(uint32_t*)&t;
}
__device__ __forceinline__ void pack_hl(float a, float b, uint32_t& h, uint32_t& l) {
    __nv_bfloat162 hh = __floats2bfloat162_rn(a, b);
    __nv_bfloat162 ll = __floats2bfloat162_rn(a - __bfloat162float(hh.x),
                                              b - __bfloat162float(hh.y));
    h = *(uint32_t*)&hh; l = *(uint32_t*)&ll;
}

// bank-XOR swizzle for 64B rows of bf16 (4 x 16B chunks per row)
#define SW64(r, c16) ((r) * 64 + ((((c16)) ^ (((r) >> 1) & 3)) << 4))
// chunk-XOR swizzle for 128B rows of bf16 (8 x 16B chunks per row)
#define SW128R(r, c16) ((r) * 128 + ((((c16)) ^ ((r) & 7)) << 4))

// ---------------- merged prep: split_X | transW | bias_cat ----------------
__global__ void prep_all(const float* __restrict__ X, ProjArgs pa) {
    __shared__ float tile[32][33];
    const int bx = blockIdx.x;
    const int tid = threadIdx.x;
    if (bx < 4096) {
        int t = bx * 256 + tid;
        float4 v = *(const float4*)&X[(size_t)t * 4];
        __nv_bfloat16 h, l;
        split2(v.x, h, l); g_Xh[(size_t)t*4+0] = h; g_Xl[(size_t)t*4+0] = l;
        split2(v.y, h, l); g_Xh[(size_t)t*4+1] = h; g_Xl[(size_t)t*4+1] = l;
        split2(v.z, h, l); g_Xh[(size_t)t*4+2] = h; g_Xl[(size_t)t*4+2] = l;
        split2(v.w, h, l); g_Xh[(size_t)t*4+3] = h; g_Xl[(size_t)t*4+3] = l;
    } else if (bx < 8192) {
        const int y = bx - 4096;
        const int nb = y & 15, kb = (y >> 4) & 31, w = y >> 9;
        const float* __restrict__ W = pa.w[w];
        const int tx = tid & 31, ty0 = tid >> 5;
#pragma unroll
        for (int i = 0; i < 4; i++) {
            int ty = ty0 + 8 * i;
            tile[ty][tx] = W[(size_t)(kb * 32 + ty) * 512 + nb * 32 + tx];
        }
        __syncthreads();
#pragma unroll
        for (int i = 0; i < 4; i++) {
            int ty = ty0 + 8 * i;
            __nv_bfloat16 h, l; split2(tile[tx][ty], h, l);
            size_t o = (size_t)(w * 512 + nb * 32 + ty) * HID + kb * 32 + tx;
            g_Wth[o] = h; g_Wtl[o] = l;
        }
    } else {
        int t = (bx - 8192) * 256 + tid;
        g_bias[t] = pa.b[t >> 9][t & 511];
    }
}

// ---------------- projection GEMM: swizzled tiles, 3-stage, 2 CTAs/SM ----------------
__global__ __launch_bounds__(256, 2) void proj_all() {
    extern __shared__ char psm[];
    float* sbias = (float*)psm;
    const uint32_t sbase = cvta_s(psm) + 1024;
    const int bx = blockIdx.x;
    const int tid = threadIdx.x, lane = tid & 31, warp = tid >> 5;
    const int wr = warp >> 1, wc = warp & 1;
    const int g = lane >> 2, tig = lane & 3;
    const bool isloc = bx < 640;
    const int bn = isloc ? (bx % 20) : ((bx - 640) % 12);
    const int bm = isloc ? (bx / 20) : ((bx - 640) / 12);
    const int nbase = isloc ? (GC + bn * 128) : (bn * 128);
    if (tid < 128) sbias[tid] = g_bias[nbase + tid];

    const int lr = tid >> 2, lc16 = tid & 3;

#define PLN(s, p) (sbase + (s) * 32768u + (p) * 8192u)
#define PLG(s, p) (sbase + (s) * 16384u + (p) * 8192u)
#define ISSL(kt, s) {                                                          \
        int k0 = (kt) * 32;                                                    \
        size_t ga = (size_t)(bm * 128 + lr) * HID + k0 + lc16 * 8;             \
        size_t gb = (size_t)(nbase + lr) * HID + k0 + lc16 * 8;                \
        uint32_t d0 = SW64(lr, lc16), d1 = SW64(lr + 64, lc16);                \
        cp16s(PLN(s,0) + d0, g_Xh + ga);                                       \
        cp16s(PLN(s,0) + d1, g_Xh + ga + 64 * HID);                            \
        cp16s(PLN(s,1) + d0, g_Wth + gb);                                      \
        cp16s(PLN(s,1) + d1, g_Wth + gb + 64 * HID);                           \
        cp16s(PLN(s,2) + d0, g_Xl + ga);                                       \
        cp16s(PLN(s,2) + d1, g_Xl + ga + 64 * HID);                            \
        cp16s(PLN(s,3) + d0, g_Wtl + gb);                                      \
        cp16s(PLN(s,3) + d1, g_Wtl + gb + 64 * HID); }
#define ISSG(kt, s) {                                                          \
        int k0 = (kt) * 32;                                                    \
        size_t ga = (size_t)(bm * 128 + lr) * HID + k0 + lc16 * 8;             \
        size_t gb = (size_t)(nbase + lr) * HID + k0 + lc16 * 8;                \
        uint32_t d0 = SW64(lr, lc16), d1 = SW64(lr + 64, lc16);                \
        cp16s(PLG(s,0) + d0, g_Xh + ga);                                       \
        cp16s(PLG(s,0) + d1, g_Xh + ga + 64 * HID);                            \
        cp16s(PLG(s,1) + d0, g_Wth + gb);                                      \
        cp16s(PLG(s,1) + d1, g_Wth + gb + 64 * HID); }

    float c[2][8][4];
#pragma unroll
    for (int mf = 0; mf < 2; mf++)
#pragma unroll
        for (int nf = 0; nf < 8; nf++)
#pragma unroll
            for (int i = 0; i < 4; i++) c[mf][nf][i] = 0.f;

    if (isloc) {
        ISSL(0, 0); asm volatile("cp.async.commit_group;");
        ISSL(1, 1); asm volatile("cp.async.commit_group;");
        for (int kt = 0; kt < 32; kt++) {
            const int s = kt % 3;
            asm volatile("cp.async.wait_group 1;");
            __syncthreads();
            if (kt + 2 < 32) { ISSL(kt + 2, (kt + 2) % 3); }
            asm volatile("cp.async.commit_group;");

            uint32_t ah[2][2][4], al[2][2][4];
#pragma unroll
            for (int mf = 0; mf < 2; mf++)
#pragma unroll
                for (int ks = 0; ks < 2; ks++) {
                    int row = wr * 32 + mf * 16 + (lane & 15);
                    int c16 = ks * 2 + (lane >> 4);
                    ldsm_x4(ah[mf][ks], PLN(s, 0) + SW64(row, c16));
                    ldsm_x4(al[mf][ks], PLN(s, 2) + SW64(row, c16));
                }
#pragma unroll
            for (int nfp = 0; nfp < 4; nfp++) {
#pragma unroll
                for (int ks = 0; ks < 2; ks++) {
                    uint32_t bh4[4], bl4[4];
                    int row = wc * 64 + nfp * 16 + (lane & 15);
                    int c16 = ks * 2 + (lane >> 4);
                    ldsm_x4(bh4, PLN(s, 1) + SW64(row, c16));
                    ldsm_x4(bl4, PLN(s, 3) + SW64(row, c16));
#pragma unroll
                    for (int mf = 0; mf < 2; mf++) {
                        mma_bf16b(c[mf][2 * nfp],     ah[mf][ks], bh4[0], bh4[2]);
                        mma_bf16b(c[mf][2 * nfp],     al[mf][ks], bh4[0], bh4[2]);
                        mma_bf16b(c[mf][2 * nfp],     ah[mf][ks], bl4[0], bl4[2]);
                        mma_bf16b(c[mf][2 * nfp + 1], ah[mf][ks], bh4[1], bh4[3]);
                        mma_bf16b(c[mf][2 * nfp + 1], al[mf][ks], bh4[1], bh4[3]);
                        mma_bf16b(c[mf][2 * nfp + 1], ah[mf][ks], bl4[1], bl4[3]);
                    }
                }
            }
        }
    } else {
        ISSG(0, 0); asm volatile("cp.async.commit_group;");
        ISSG(1, 1); asm volatile("cp.async.commit_group;");
        for (int kt = 0; kt < 32; kt++) {
            const int s = kt % 3;
            asm volatile("cp.async.wait_group 1;");
            __syncthreads();
            if (kt + 2 < 32) { ISSG(kt + 2, (kt + 2) % 3); }
            asm volatile("cp.async.commit_group;");

            uint32_t ah[2][2][4];
#pragma unroll
            for (int mf = 0; mf < 2; mf++)
#pragma unroll
                for (int ks = 0; ks < 2; ks++) {
                    int row = wr * 32 + mf * 16 + (lane & 15);
                    int c16 = ks * 2 + (lane >> 4);
                    ldsm_x4(ah[mf][ks], PLG(s, 0) + SW64(row, c16));
                }
#pragma unroll
            for (int nfp = 0; nfp < 4; nfp++) {
#pragma unroll
                for (int ks = 0; ks < 2; ks++) {
                    uint32_t b4[4];
                    int row = wc * 64 + nfp * 16 + (lane & 15);
                    int c16 = ks * 2 + (lane >> 4);
                    ldsm_x4(b4, PLG(s, 1) + SW64(row, c16));
#pragma unroll
                    for (int mf = 0; mf < 2; mf++) {
                        mma_bf16b(c[mf][2 * nfp],     ah[mf][ks], b4[0], b4[2]);
                        mma_bf16b(c[mf][2 * nfp + 1], ah[mf][ks], b4[1], b4[3]);
                    }
                }
            }
        }
    }

#pragma unroll
    for (int mf = 0; mf < 2; mf++)
#pragma unroll
        for (int nf = 0; nf < 8; nf++) {
            int lcol = wc * 64 + nf * 8 + 2 * tig;
            int r0 = bm * 128 + wr * 32 + mf * 16 + g;
            float v0 = c[mf][nf][0] + sbias[lcol];
            float v1 = c[mf][nf][1] + sbias[lcol + 1];
            float v2 = c[mf][nf][2] + sbias[lcol];
            float v3 = c[mf][nf][3] + sbias[lcol + 1];
            if (isloc) {
                int fc = bn * 128 + lcol;
                g_Pf[(size_t)r0 * LC + fc]           = v0;
                g_Pf[(size_t)r0 * LC + fc + 1]       = v1;
                g_Pf[(size_t)(r0 + 8) * LC + fc]     = v2;
                g_Pf[(size_t)(r0 + 8) * LC + fc + 1] = v3;
            } else {
                int gcol = bn * 128 + lcol;
                *(uint32_t*)&g_Pg[(size_t)r0 * GC + gcol]       = pack_bf16(v0, v1);
                *(uint32_t*)&g_Pg[(size_t)(r0 + 8) * GC + gcol] = pack_bf16(v2, v3);
            }
        }
}

// ---------------- merged: M partials [0,128) | prep_local [128,2176) ----------------
__global__ __launch_bounds__(256) void mpart_prep() {
    __shared__ float Ls[64 * 68];
    const int bx = blockIdx.x;
    const int tid = threadIdx.x;
    if (bx < 128) {
        const int bh = bx & 15, b = bh >> 3, h = bh & 7;
        const int part = bx >> 4;
        const int e = tid & 63, d0 = tid >> 6;
        float acc[16];
#pragma unroll
        for (int i = 0; i < 16; i++) acc[i] = 0.f;
        const int colbase = 512 + h * 64;
        for (int t = 0; t < 4; t++) {
            const int s0 = (part * 4 + t) * 64;
            __syncthreads();
#pragma unroll
            for (int ch = 0; ch < 4; ch++) {
                int idx = tid + 256 * ch;
                int r = idx >> 4, c4 = (idx & 15) * 4;
                *(float4*)&Ls[r * 68 + c4] =
                    *(const float4*)&g_Pf[(size_t)(b * SEQ + s0 + r) * LC + colbase + c4];
            }
            __syncthreads();
            for (int r = 0; r < 64; r++) {
                float le = Ls[r * 68 + e];
#pragma unroll
                for (int i = 0; i < 16; i++)
                    acc[i] += Ls[r * 68 + d0 + 4 * i] * le;
            }
        }
#pragma unroll
        for (int i = 0; i < 16; i++)
            g_Mpart[((size_t)part * 16 + bh) * 4096 + (d0 + 4 * i) * 64 + e] = acc[i];
    } else {
        int t = (bx - 128) * 256 + tid;
        int r = t >> 7, c4 = (t & 127) * 4;
        size_t grow = (size_t)r * LC;
        size_t po = (size_t)r * 512 + c4;
        float4 k = *(const float4*)&g_Pf[grow + 1024 + c4];
        __nv_bfloat162 h01, h23, l01, l23;
        split2(k.x, h01.x, l01.x); split2(k.y, h01.y, l01.y);
        split2(k.z, h23.x, l23.x); split2(k.w, h23.y, l23.y);
        *(__nv_bfloat162*)&g_K2h[po]     = h01;
        *(__nv_bfloat162*)&g_K2h[po + 2] = h23;
        *(__nv_bfloat162*)&g_K2l[po]     = l01;
        *(__nv_bfloat162*)&g_K2l[po + 2] = l23;
        float4 v1 = *(const float4*)&g_Pf[grow + 1536 + c4];
        float4 v2 = *(const float4*)&g_Pf[grow + 2048 + c4];
        split2(v1.x + v2.x, h01.x, l01.x); split2(v1.y + v2.y, h01.y, l01.y);
        split2(v1.z + v2.z, h23.x, l23.x); split2(v1.w + v2.w, h23.y, l23.y);
        *(__nv_bfloat162*)&g_Vmh[po]     = h01;
        *(__nv_bfloat162*)&g_Vmh[po + 2] = h23;
        *(__nv_bfloat162*)&g_Vml[po]     = l01;
        *(__nv_bfloat162*)&g_Vml[po + 2] = l23;
    }
}

__global__ __launch_bounds__(256) void reduce_M() {
    const int t = blockIdx.x * 256 + threadIdx.x;
    const int bh = t >> 12, idx = t & 4095;
    float s = 0.f;
#pragma unroll
    for (int p = 0; p < 8; p++) s += g_Mpart[((size_t)p * 16 + bh) * 4096 + idx];
    g_M[(size_t)bh * 4096 + idx] = s;
}

// ---------------- LQ' = LQ @ M (fp32, in place) ----------------
__global__ __launch_bounds__(256) void lq_update() {
    __shared__ float Ms[64 * 65];
    __shared__ float Ls[64 * 68];
    const int rb = blockIdx.x, h = blockIdx.y;
    const int row0 = rb * 64, b = row0 >> 11, bh = b * 8 + h;
    const int tid = threadIdx.x;
    const int colbase = h * 64;
#pragma unroll
    for (int ch = 0; ch < 16; ch++) {
        int idx = tid + 256 * ch;
        Ms[(idx >> 6) * 65 + (idx & 63)] = g_M[(size_t)bh * 4096 + idx];
    }
#pragma unroll
    for (int ch = 0; ch < 4; ch++) {
        int idx = tid + 256 * ch;
        int r = idx >> 4, c4 = (idx & 15) * 4;
        *(float4*)&Ls[r * 68 + c4] =
            *(const float4*)&g_Pf[(size_t)(row0 + r) * LC + colbase + c4];
    }
    __syncthreads();
    const int e = tid & 63, r0 = tid >> 6;
    float acc[16];
#pragma unroll
    for (int i = 0; i < 16; i++) acc[i] = 0.f;
    for (int d = 0; d < 64; d++) {
        float mv = Ms[d * 65 + e];
#pragma unroll
        for (int i = 0; i < 16; i++)
            acc[i] += Ls[(r0 + 4 * i) * 68 + d] * mv;
    }
#pragma unroll
    for (int i = 0; i < 16; i++)
        g_Pf[(size_t)(row0 + r0 + 4 * i) * LC + colbase + e] = acc[i];
}

// ---------------- merged flash: [0,256) local, [256,512) global ----------------
__global__ __launch_bounds__(256, 2) void flash_all(const float* __restrict__ mask,
                                                    float* __restrict__ out) {
    extern __shared__ char fsm[];
    const int tid = threadIdx.x, lane = tid & 31, warp = tid >> 5;
    const int g = lane >> 2, tig = lane & 3;
    const int bx = blockIdx.x;
    const int lr = tid >> 2, lch = tid & 3;

    if (bx < 256) {
        // ===== local: swizzled 8KB planes, 3-stage, 1 sync/iter =====
        const uint32_t lbase = cvta_s(fsm);
#define LFS(s, p) (lbase + (s) * 32768u + (p) * 8192u)   // p: 0=KH 1=KL 2=VH 3=VL
        const int qb = bx & 15, by = bx >> 4;
        const int b = by >> 3, h = by & 7;
        const int rowbase = b * SEQ;

#define LF_ISS(kt, s) {                                                        \
        int c0 = lch * 2, c1 = lch * 2 + 1;                                    \
        size_t go = (size_t)(rowbase + (kt) * 64 + lr) * 512 + h * 64 + c0 * 8; \
        uint32_t d0, d1;                                                       \
        d0 = SW128R(lr, c0); d1 = SW128R(lr, c1);                              \
        cp16s(LFS(s,0) + d0, &g_K2h[go]);                                      \
        cp16s(LFS(s,0) + d1, &g_K2h[go + 8]);                                  \
        cp16s(LFS(s,1) + d0, &g_K2l[go]);                                      \
        cp16s(LFS(s,1) + d1, &g_K2l[go + 8]);                                  \
        cp16s(LFS(s,2) + d0, &g_Vmh[go]);                                      \
        cp16s(LFS(s,2) + d1, &g_Vmh[go + 8]);                                  \
        cp16s(LFS(s,3) + d0, &g_Vml[go]);                                      \
        cp16s(LFS(s,3) + d1, &g_Vml[go + 8]); }

        uint32_t qh[4][4], ql[4][4];
        const int qr0 = rowbase + qb * 128 + warp * 16 + g;
        const float* P0 = &g_Pf[(size_t)qr0 * LC + h * 64];
        const float* P1 = &g_Pf[(size_t)(qr0 + 8) * LC + h * 64];
#pragma unroll
        for (int ks = 0; ks < 4; ks++) {
            int c0 = ks * 16 + 2 * tig;
            pack_hl(P0[c0],     P0[c0 + 1], qh[ks][0], ql[ks][0]);
            pack_hl(P1[c0],     P1[c0 + 1], qh[ks][1], ql[ks][1]);
            pack_hl(P0[c0 + 8], P0[c0 + 9], qh[ks][2], ql[ks][2]);
            pack_hl(P1[c0 + 8], P1[c0 + 9], qh[ks][3], ql[ks][3]);
        }

        LF_ISS(0, 0); asm volatile("cp.async.commit_group;");
        LF_ISS(1, 1); asm volatile("cp.async.commit_group;");

        float of[8][4];
#pragma unroll
        for (int nf = 0; nf < 8; nf++)
#pragma unroll
            for (int i = 0; i < 4; i++) of[nf][i] = 0.f;
        float m0 = -1e30f, m1 = -1e30f, l0 = 0.f, l1 = 0.f;

        for (int kt = 0; kt < 32; kt++) {
            const int s = kt % 3;
            asm volatile("cp.async.wait_group 1;");
            __syncthreads();
            if (kt + 2 < 32) { LF_ISS(kt + 2, (kt + 2) % 3); }
            asm volatile("cp.async.commit_group;");

            float sf[8][4];
#pragma unroll
            for (int nfp = 0; nfp < 4; nfp++) {
#pragma unroll
                for (int i = 0; i < 4; i++) { sf[2*nfp][i] = 0.f; sf[2*nfp+1][i] = 0.f; }
#pragma unroll
                for (int ks = 0; ks < 4; ks++) {
                    uint32_t kh4[4], kl4[4];
                    int row = nfp * 16 + (lane & 15);
                    int c16 = ks * 2 + (lane >> 4);
                    ldsm_x4(kh4, LFS(s, 0) + SW128R(row, c16));
                    ldsm_x4(kl4, LFS(s, 1) + SW128R(row, c16));
                    mma_bf16b(sf[2 * nfp],     qh[ks], kh4[0], kh4[2]);
                    mma_bf16b(sf[2 * nfp],     ql[ks], kh4[0], kh4[2]);
                    mma_bf16b(sf[2 * nfp],     qh[ks], kl4[0], kl4[2]);
                    mma_bf16b(sf[2 * nfp + 1], qh[ks], kh4[1], kh4[3]);
                    mma_bf16b(sf[2 * nfp + 1], ql[ks], kh4[1], kh4[3]);
                    mma_bf16b(sf[2 * nfp + 1], qh[ks], kl4[1], kl4[3]);
                }
            }

            float mx0 = -1e30f, mx1 = -1e30f;
#pragma unroll
            for (int nf = 0; nf < 8; nf++) {
                sf[nf][0] *= 0.125f; sf[nf][1] *= 0.125f;
                sf[nf][2] *= 0.125f; sf[nf][3] *= 0.125f;
                mx0 = fmaxf(mx0, fmaxf(sf[nf][0], sf[nf][1]));
                mx1 = fmaxf(mx1, fmaxf(sf[nf][2], sf[nf][3]));
            }
            mx0 = fmaxf(mx0, __shfl_xor_sync(~0u, mx0, 1));
            mx0 = fmaxf(mx0, __shfl_xor_sync(~0u, mx0, 2));
            mx1 = fmaxf(mx1, __shfl_xor_sync(~0u, mx1, 1));
            mx1 = fmaxf(mx1, __shfl_xor_sync(~0u, mx1, 2));
            float mn0 = fmaxf(m0, mx0), mn1 = fmaxf(m1, mx1);
            float cr0 = __expf(m0 - mn0), cr1 = __expf(m1 - mn1);
            m0 = mn0; m1 = mn1;

            float ps0 = 0.f, ps1 = 0.f;
            uint32_t pah[4][4];
#pragma unroll
            for (int nf = 0; nf < 8; nf++) {
                float p0 = __expf(sf[nf][0] - mn0), p1 = __expf(sf[nf][1] - mn0);
                float p2 = __expf(sf[nf][2] - mn1), p3 = __expf(sf[nf][3] - mn1);
                ps0 += p0 + p1; ps1 += p2 + p3;
                int ks = nf >> 1;
                if (nf & 1) { pah[ks][2] = pack_bf16(p0, p1); pah[ks][3] = pack_bf16(p2, p3); }
                else        { pah[ks][0] = pack_bf16(p0, p1); pah[ks][1] = pack_bf16(p2, p3); }
            }
            ps0 += __shfl_xor_sync(~0u, ps0, 1); ps0 += __shfl_xor_sync(~0u, ps0, 2);
            ps1 += __shfl_xor_sync(~0u, ps1, 1); ps1 += __shfl_xor_sync(~0u, ps1, 2);
            l0 = l0 * cr0 + ps0; l1 = l1 * cr1 + ps1;
#pragma unroll
            for (int nf = 0; nf < 8; nf++) {
                of[nf][0] *= cr0; of[nf][1] *= cr0; of[nf][2] *= cr1; of[nf][3] *= cr1;
            }
#pragma unroll
            for (int nfp = 0; nfp < 4; nfp++)
#pragma unroll
                for (int ks = 0; ks < 4; ks++) {
                    uint32_t vh4[4], vl4[4];
                    int row = ks * 16 + (lane & 15);
                    int c16 = nfp * 2 + (lane >> 4);
                    ldsm_x4t(vh4, LFS(s, 2) + SW128R(row, c16));
                    ldsm_x4t(vl4, LFS(s, 3) + SW128R(row, c16));
                    mma_bf16b(of[2 * nfp],     pah[ks], vh4[0], vh4[1]);
                    mma_bf16b(of[2 * nfp],     pah[ks], vl4[0], vl4[1]);
                    mma_bf16b(of[2 * nfp + 1], pah[ks], vh4[2], vh4[3]);
                    mma_bf16b(of[2 * nfp + 1], pah[ks], vl4[2], vl4[3]);
                }
        }

        const float inv0 = 1.f / l0, inv1 = 1.f / l1;
        const int r0 = rowbase + qb * 128 + warp * 16 + g;
#pragma unroll
        for (int nf = 0; nf < 8; nf++) {
            int col = (8 + h) * 64 + nf * 8 + 2 * tig;
            out[(size_t)r0 * HID + col]           = of[nf][0] * inv0;
            out[(size_t)r0 * HID + col + 1]       = of[nf][1] * inv0;
            out[(size_t)(r0 + 8) * HID + col]     = of[nf][2] * inv1;
            out[(size_t)(r0 + 8) * HID + col + 1] = of[nf][3] * inv1;
        }
    } else {
        __nv_bfloat16* Qs = (__nv_bfloat16*)fsm;
        float* maskS = (float*)(fsm + 18432);
#define GF_K(s) ((__nv_bfloat16*)(fsm + 26624 + (s) * 18432))
#define GF_V(s) ((__nv_bfloat16*)(fsm + 26624 + (s) * 18432 + 9216))
        const int y = bx - 256;
        const int qb = y & 15, by = y >> 4;
        const int b = by >> 3, h = by & 7;
        const int qcol = h * 64, kcol = 512 + h * 64, vcol = 1024 + h * 64;
        const int rowbase = b * SEQ;

#define GF_ISS(kt, s) {                                                        \
        size_t grow = (size_t)(rowbase + (kt) * 64 + lr) * GC;                 \
        cp16(GF_K(s) + lr * 72 + lch * 16,     &g_Pg[grow + kcol + lch * 16]); \
        cp16(GF_K(s) + lr * 72 + lch * 16 + 8, &g_Pg[grow + kcol + lch * 16 + 8]); \
        cp16(GF_V(s) + lr * 72 + lch * 16,     &g_Pg[grow + vcol + lch * 16]); \
        cp16(GF_V(s) + lr * 72 + lch * 16 + 8, &g_Pg[grow + vcol + lch * 16 + 8]); }

#pragma unroll
        for (int i = 0; i < 8; i++) maskS[tid + 256 * i] = mask[b * SEQ + tid + 256 * i];
#pragma unroll
        for (int i = 0; i < 4; i++) {
            int idx = tid + 256 * i;
            int r = idx >> 3, ch = idx & 7;
            *(uint4*)&Qs[r * 72 + ch * 8] =
                *(const uint4*)&g_Pg[(size_t)(rowbase + qb * 128 + r) * GC + qcol + ch * 8];
        }
        GF_ISS(0, 0); asm volatile("cp.async.commit_group;");
        GF_ISS(1, 1); asm volatile("cp.async.commit_group;");
        __syncthreads();

        uint32_t qf[4][4];
#pragma unroll
        for (int ks = 0; ks < 4; ks++) {
            int row = warp * 16 + (lane & 15);
            int col = ks * 16 + (lane >> 4) * 8;
            ldsm_x4(qf[ks], cvta_s(&Qs[row * 72 + col]));
        }

        float of[8][4];
#pragma unroll
        for (int nf = 0; nf < 8; nf++)
#pragma unroll
            for (int i = 0; i < 4; i++) of[nf][i] = 0.f;
        float m0 = -1e30f, m1 = -1e30f, l0 = 0.f, l1 = 0.f;

        for (int kt = 0; kt < 32; kt++) {
            const int s = kt % 3;
            asm volatile("cp.async.wait_group 1;");
            __syncthreads();
            if (kt + 2 < 32) { GF_ISS(kt + 2, (kt + 2) % 3); }
            asm volatile("cp.async.commit_group;");

            __nv_bfloat16* Ks = GF_K(s);
            __nv_bfloat16* Vs = GF_V(s);

            float sf[8][4];
#pragma unroll
            for (int nfp = 0; nfp < 4; nfp++) {
#pragma unroll
                for (int i = 0; i < 4; i++) { sf[2*nfp][i] = 0.f; sf[2*nfp+1][i] = 0.f; }
#pragma unroll
                for (int ks = 0; ks < 4; ks++) {
                    uint32_t k4[4];
                    int row = nfp * 16 + (lane & 15);
                    int col = ks * 16 + (lane >> 4) * 8;
                    ldsm_x4(k4, cvta_s(&Ks[row * 72 + col]));
                    mma_bf16b(sf[2 * nfp],     qf[ks], k4[0], k4[2]);
                    mma_bf16b(sf[2 * nfp + 1], qf[ks], k4[1], k4[3]);
                }
            }

            float mx0 = -1e30f, mx1 = -1e30f;
#pragma unroll
            for (int nf = 0; nf < 8; nf++) {
                float a0 = maskS[kt * 64 + nf * 8 + 2 * tig];
                float a1 = maskS[kt * 64 + nf * 8 + 2 * tig + 1];
                sf[nf][0] = sf[nf][0] * 0.125f + a0;
                sf[nf][1] = sf[nf][1] * 0.125f + a1;
                sf[nf][2] = sf[nf][2] * 0.125f + a0;
                sf[nf][3] = sf[nf][3] * 0.125f + a1;
                mx0 = fmaxf(mx0, fmaxf(sf[nf][0], sf[nf][1]));
                mx1 = fmaxf(mx1, fmaxf(sf[nf][2], sf[nf][3]));
            }
            mx0 = fmaxf(mx0, __shfl_xor_sync(~0u, mx0, 1));
            mx0 = fmaxf(mx0, __shfl_xor_sync(~0u, mx0, 2));
            mx1 = fmaxf(mx1, __shfl_xor_sync(~0u, mx1, 1));
            mx1 = fmaxf(mx1, __shfl_xor_sync(~0u, mx1, 2));
            float mn0 = fmaxf(m0, mx0), mn1 = fmaxf(m1, mx1);
            float cr0 = __expf(m0 - mn0), cr1 = __expf(m1 - mn1);
            m0 = mn0; m1 = mn1;

            float ps0 = 0.f, ps1 = 0.f;
            uint32_t pa[4][4];
#pragma unroll
            for (int nf = 0; nf < 8; nf++) {
                float p0 = __expf(sf[nf][0] - mn0), p1 = __expf(sf[nf][1] - mn0);
                float p2 = __expf(sf[nf][2] - mn1), p3 = __expf(sf[nf][3] - mn1);
                ps0 += p0 + p1; ps1 += p2 + p3;
                int ks = nf >> 1;
                if (nf & 1) { pa[ks][2] = pack_bf16(p0, p1); pa[ks][3] = pack_bf16(p2, p3); }
                else        { pa[ks][0] = pack_bf16(p0, p1); pa[ks][1] = pack_bf16(p2, p3); }
            }
            ps0 += __shfl_xor_sync(~0u, ps0, 1); ps0 += __shfl_xor_sync(~0u, ps0, 2);
            ps1 += __shfl_xor_sync(~0u, ps1, 1); ps1 += __shfl_xor_sync(~0u, ps1, 2);
            l0 = l0 * cr0 + ps0; l1 = l1 * cr1 + ps1;
#pragma unroll
            for (int nf = 0; nf < 8; nf++) {
                of[nf][0] *= cr0; of[nf][1] *= cr0; of[nf][2] *= cr1; of[nf][3] *= cr1;
            }
#pragma unroll
            for (int nfp = 0; nfp < 4; nfp++)
#pragma unroll
                for (int ks = 0; ks < 4; ks++) {
                    uint32_t v4[4];
                    int row = ks * 16 + (lane & 15);
                    int col = nfp * 16 + (lane >> 4) * 8;
                    ldsm_x4t(v4, cvta_s(&Vs[row * 72 + col]));
                    mma_bf16b(of[2 * nfp],     pa[ks], v4[0], v4[1]);
                    mma_bf16b(of[2 * nfp + 1], pa[ks], v4[2], v4[3]);
                }
        }

        const float inv0 = 1.f / l0, inv1 = 1.f / l1;
        const int r0 = rowbase + qb * 128 + warp * 16 + g;
#pragma unroll
        for (int nf = 0; nf < 8; nf++) {
            int col = h * 64 + nf * 8 + 2 * tig;
            out[(size_t)r0 * HID + col]           = of[nf][0] * inv0;
            out[(size_t)r0 * HID + col + 1]       = of[nf][1] * inv0;
            out[(size_t)(r0 + 8) * HID + col]     = of[nf][2] * inv1;
            out[(size_t)(r0 + 8) * HID + col + 1] = of[nf][3] * inv1;
        }
    }
}

// ---------------------------------------------------------------------------
extern "C" void kernel_launch(void* const* d_in, const int* in_sizes, int n_in,
                              void* d_out, int out_size) {
    (void)in_sizes; (void)n_in; (void)out_size;
    const float* X    = (const float*)d_in[0];
    const float* mask = (const float*)d_in[1];
    ProjArgs pa;
    for (int i = 0; i < 8; i++) {
        pa.w[i] = (const float*)d_in[2 + 2 * i];
        pa.b[i] = (const float*)d_in[3 + 2 * i];
    }
    float* out = (float*)d_out;

    const int PASMEM = 1024 + 3 * 32768;    // 99328
    const int FASMEM = 3 * 32768;           // 98304 (local path; global uses 81920)
    cudaFuncSetAttribute(proj_all, cudaFuncAttributeMaxDynamicSharedMemorySize, PASMEM);
    cudaFuncSetAttribute(flash_all, cudaFuncAttributeMaxDynamicSharedMemorySize, FASMEM);

    prep_all<<<8208, 256>>>(X, pa);
    proj_all<<<1024, 256, PASMEM>>>();
    mpart_prep<<<2176, 256>>>();
    reduce_M<<<256, 256>>>();
    lq_update<<<dim3(64, 8), 256>>>();
    flash_all<<<512, 256, FASMEM>>>(mask, out);
}

// round 14
// speedup vs baseline: 1.0793x; 1.0793x over previous
#include <cuda_runtime.h>
#include <cuda_bf16.h>
#include <cstdint>

#define SEQ 2048
#define NROWS 4096
#define HID 1024
#define GC 1536   // global proj cols: Q 0, K 512, V 1024
#define LC 2048   // local proj cols: LQ 0, LK1 512, LK2 1024, LVm 1536 (lv1+lv2 combined)

__device__ __nv_bfloat16 g_Xh[(size_t)NROWS * HID];
__device__ __nv_bfloat16 g_Xl[(size_t)NROWS * HID];
__device__ __nv_bfloat16 g_Wth[(size_t)3584 * HID];   // 7 effective W, transposed [n][k]
__device__ __nv_bfloat16 g_Wtl[(size_t)3584 * HID];
__device__ float g_bias[3584];
__device__ __nv_bfloat16 g_Pg[(size_t)NROWS * GC];    // global projections bf16
__device__ float g_Pf[(size_t)NROWS * LC];            // local projections fp32
__device__ float g_Mpart[8 * 16 * 64 * 64];
__device__ float g_M[16 * 64 * 64];
__device__ __nv_bfloat16 g_K2h[(size_t)NROWS * 512];
__device__ __nv_bfloat16 g_K2l[(size_t)NROWS * 512];
__device__ __nv_bfloat16 g_Vmh[(size_t)NROWS * 512];
__device__ __nv_bfloat16 g_Vml[(size_t)NROWS * 512];

struct ProjArgs { const float* w[8]; const float* b[8]; };

// ---------------- helpers ----------------
__device__ __forceinline__ uint32_t cvta_s(const void* p) {
    return (uint32_t)__cvta_generic_to_shared(p);
}
__device__ __forceinline__ void cp16(void* smem, const void* gmem) {
    asm volatile("cp.async.cg.shared.global [%0], [%1], 16;"
                 :: "r"(cvta_s(smem)), "l"(gmem));
}
__device__ __forceinline__ void cp16s(uint32_t smem, const void* gmem) {
    asm volatile("cp.async.cg.shared.global [%0], [%1], 16;"
                 :: "r"(smem), "l"(gmem));
}
__device__ __forceinline__ void ldsm_x4(uint32_t r[4], uint32_t a) {
    asm volatile("ldmatrix.sync.aligned.m8n8.x4.shared.b16 {%0,%1,%2,%3}, [%4];"
                 : "=r"(r[0]), "=r"(r[1]), "=r"(r[2]), "=r"(r[3]) : "r"(a));
}
__device__ __forceinline__ void ldsm_x4t(uint32_t r[4], uint32_t a) {
    asm volatile("ldmatrix.sync.aligned.m8n8.x4.trans.shared.b16 {%0,%1,%2,%3}, [%4];"
                 : "=r"(r[0]), "=r"(r[1]), "=r"(r[2]), "=r"(r[3]) : "r"(a));
}
__device__ __forceinline__ void mma_bf16b(float c[4], const uint32_t a[4], uint32_t b0, uint32_t b1) {
    asm volatile("mma.sync.aligned.m16n8k16.row.col.f32.bf16.bf16.f32 "
                 "{%0,%1,%2,%3},{%4,%5,%6,%7},{%8,%9},{%0,%1,%2,%3};"
                 : "+f"(c[0]), "+f"(c[1]), "+f"(c[2]), "+f"(c[3])
                 : "r"(a[0]), "r"(a[1]), "r"(a[2]), "r"(a[3]), "r"(b0), "r"(b1));
}
__device__ __forceinline__ void split2(float x, __nv_bfloat16& h, __nv_bfloat16& l) {
    h = __float2bfloat16_rn(x);
    l = __float2bfloat16_rn(x - __bfloat162float(h));
}
__device__ __forceinline__ uint32_t pack_bf16(float a, float b) {
    __nv_bfloat162 t = __floats2bfloat162_rn(a, b);
    return *(uint32_t*)&t;
}
__device__ __forceinline__ void pack_hl(float a, float b, uint32_t& h, uint32_t& l) {
    __nv_bfloat162 hh = __floats2bfloat162_rn(a, b);
    __nv_bfloat162 ll = __floats2bfloat162_rn(a - __bfloat162float(hh.x),
                                              b - __bfloat162float(hh.y));
    h = *(uint32_t*)&hh; l = *(uint32_t*)&ll;
}

// bank-XOR swizzle for 64B rows of bf16 (4 x 16B chunks per row)
#define SW64(r, c16) ((r) * 64 + ((((c16)) ^ (((r) >> 1) & 3)) << 4))

// ---------------- merged prep: split_X | transW (7 eff. W) | bias_cat ----------------
// grid: [0,4096) split_X, [4096,7680) transW (16*32*7), [7680,7694) bias (3584 entries)
__global__ void prep_all(const float* __restrict__ X, ProjArgs pa) {
    __shared__ float tile[32][33];
    const int bx = blockIdx.x;
    const int tid = threadIdx.x;
    if (bx < 4096) {
        int t = bx * 256 + tid;
        float4 v = *(const float4*)&X[(size_t)t * 4];
        __nv_bfloat16 h, l;
        split2(v.x, h, l); g_Xh[(size_t)t*4+0] = h; g_Xl[(size_t)t*4+0] = l;
        split2(v.y, h, l); g_Xh[(size_t)t*4+1] = h; g_Xl[(size_t)t*4+1] = l;
        split2(v.z, h, l); g_Xh[(size_t)t*4+2] = h; g_Xl[(size_t)t*4+2] = l;
        split2(v.w, h, l); g_Xh[(size_t)t*4+3] = h; g_Xl[(size_t)t*4+3] = l;
    } else if (bx < 7680) {
        const int y = bx - 4096;
        const int nb = y & 15, kb = (y >> 4) & 31, w = y >> 9;   // w 0..6
        const int tx = tid & 31, ty0 = tid >> 5;
        if (w < 6) {
            const float* __restrict__ W = pa.w[w];
#pragma unroll
            for (int i = 0; i < 4; i++) {
                int ty = ty0 + 8 * i;
                tile[ty][tx] = W[(size_t)(kb * 32 + ty) * 512 + nb * 32 + tx];
            }
        } else {
            const float* __restrict__ W6 = pa.w[6];
            const float* __restrict__ W7 = pa.w[7];
#pragma unroll
            for (int i = 0; i < 4; i++) {
                int ty = ty0 + 8 * i;
                size_t o = (size_t)(kb * 32 + ty) * 512 + nb * 32 + tx;
                tile[ty][tx] = W6[o] + W7[o];
            }
        }
        __syncthreads();
#pragma unroll
        for (int i = 0; i < 4; i++) {
            int ty = ty0 + 8 * i;
            __nv_bfloat16 h, l; split2(tile[tx][ty], h, l);
            size_t o = (size_t)(w * 512 + nb * 32 + ty) * HID + kb * 32 + tx;
            g_Wth[o] = h; g_Wtl[o] = l;
        }
    } else {
        int t = (bx - 7680) * 256 + tid;       // 0..3583
        if (t < 3584) {
            if (t < 3072) g_bias[t] = pa.b[t >> 9][t & 511];
            else          g_bias[t] = pa.b[6][t - 3072] + pa.b[7][t - 3072];
        }
    }
}

// ---------------- projection GEMM: swizzled tiles, 3-stage, 2 CTAs/SM ----------------
// grid.x = 896: [0,512) local (3-term), [512,896) global (1-term)
__global__ __launch_bounds__(256, 2) void proj_all() {
    extern __shared__ char psm[];
    float* sbias = (float*)psm;
    const uint32_t sbase = cvta_s(psm) + 1024;
    const int bx = blockIdx.x;
    const int tid = threadIdx.x, lane = tid & 31, warp = tid >> 5;
    const int wr = warp >> 1, wc = warp & 1;
    const int g = lane >> 2, tig = lane & 3;
    const bool isloc = bx < 512;
    const int bn = isloc ? (bx & 15) : ((bx - 512) % 12);
    const int bm = isloc ? (bx >> 4) : ((bx - 512) / 12);
    const int nbase = isloc ? (GC + bn * 128) : (bn * 128);
    if (tid < 128) sbias[tid] = g_bias[nbase + tid];

    const int lr = tid >> 2, lc16 = tid & 3;

#define PLN(s, p) (sbase + (s) * 32768u + (p) * 8192u)
#define PLG(s, p) (sbase + (s) * 16384u + (p) * 8192u)
#define ISSL(kt, s) {                                                          \
        int k0 = (kt) * 32;                                                    \
        size_t ga = (size_t)(bm * 128 + lr) * HID + k0 + lc16 * 8;             \
        size_t gb = (size_t)(nbase + lr) * HID + k0 + lc16 * 8;                \
        uint32_t d0 = SW64(lr, lc16), d1 = SW64(lr + 64, lc16);                \
        cp16s(PLN(s,0) + d0, g_Xh + ga);                                       \
        cp16s(PLN(s,0) + d1, g_Xh + ga + 64 * HID);                            \
        cp16s(PLN(s,1) + d0, g_Wth + gb);                                      \
        cp16s(PLN(s,1) + d1, g_Wth + gb + 64 * HID);                           \
        cp16s(PLN(s,2) + d0, g_Xl + ga);                                       \
        cp16s(PLN(s,2) + d1, g_Xl + ga + 64 * HID);                            \
        cp16s(PLN(s,3) + d0, g_Wtl + gb);                                      \
        cp16s(PLN(s,3) + d1, g_Wtl + gb + 64 * HID); }
#define ISSG(kt, s) {                                                          \
        int k0 = (kt) * 32;                                                    \
        size_t ga = (size_t)(bm * 128 + lr) * HID + k0 + lc16 * 8;             \
        size_t gb = (size_t)(nbase + lr) * HID + k0 + lc16 * 8;                \
        uint32_t d0 = SW64(lr, lc16), d1 = SW64(lr + 64, lc16);                \
        cp16s(PLG(s,0) + d0, g_Xh + ga);                                       \
        cp16s(PLG(s,0) + d1, g_Xh + ga + 64 * HID);                            \
        cp16s(PLG(s,1) + d0, g_Wth + gb);                                      \
        cp16s(PLG(s,1) + d1, g_Wth + gb + 64 * HID); }

    float c[2][8][4];
#pragma unroll
    for (int mf = 0; mf < 2; mf++)
#pragma unroll
        for (int nf = 0; nf < 8; nf++)
#pragma unroll
            for (int i = 0; i < 4; i++) c[mf][nf][i] = 0.f;

    if (isloc) {
        ISSL(0, 0); asm volatile("cp.async.commit_group;");
        ISSL(1, 1); asm volatile("cp.async.commit_group;");
        for (int kt = 0; kt < 32; kt++) {
            const int s = kt % 3;
            asm volatile("cp.async.wait_group 1;");
            __syncthreads();
            if (kt + 2 < 32) { ISSL(kt + 2, (kt + 2) % 3); }
            asm volatile("cp.async.commit_group;");

            uint32_t ah[2][2][4], al[2][2][4];
#pragma unroll
            for (int mf = 0; mf < 2; mf++)
#pragma unroll
                for (int ks = 0; ks < 2; ks++) {
                    int row = wr * 32 + mf * 16 + (lane & 15);
                    int c16 = ks * 2 + (lane >> 4);
                    ldsm_x4(ah[mf][ks], PLN(s, 0) + SW64(row, c16));
                    ldsm_x4(al[mf][ks], PLN(s, 2) + SW64(row, c16));
                }
#pragma unroll
            for (int nfp = 0; nfp < 4; nfp++) {
#pragma unroll
                for (int ks = 0; ks < 2; ks++) {
                    uint32_t bh4[4], bl4[4];
                    int row = wc * 64 + nfp * 16 + (lane & 15);
                    int c16 = ks * 2 + (lane >> 4);
                    ldsm_x4(bh4, PLN(s, 1) + SW64(row, c16));
                    ldsm_x4(bl4, PLN(s, 3) + SW64(row, c16));
#pragma unroll
                    for (int mf = 0; mf < 2; mf++) {
                        mma_bf16b(c[mf][2 * nfp],     ah[mf][ks], bh4[0], bh4[2]);
                        mma_bf16b(c[mf][2 * nfp],     al[mf][ks], bh4[0], bh4[2]);
                        mma_bf16b(c[mf][2 * nfp],     ah[mf][ks], bl4[0], bl4[2]);
                        mma_bf16b(c[mf][2 * nfp + 1], ah[mf][ks], bh4[1], bh4[3]);
                        mma_bf16b(c[mf][2 * nfp + 1], al[mf][ks], bh4[1], bh4[3]);
                        mma_bf16b(c[mf][2 * nfp + 1], ah[mf][ks], bl4[1], bl4[3]);
                    }
                }
            }
        }
    } else {
        ISSG(0, 0); asm volatile("cp.async.commit_group;");
        ISSG(1, 1); asm volatile("cp.async.commit_group;");
        for (int kt = 0; kt < 32; kt++) {
            const int s = kt % 3;
            asm volatile("cp.async.wait_group 1;");
            __syncthreads();
            if (kt + 2 < 32) { ISSG(kt + 2, (kt + 2) % 3); }
            asm volatile("cp.async.commit_group;");

            uint32_t ah[2][2][4];
#pragma unroll
            for (int mf = 0; mf < 2; mf++)
#pragma unroll
                for (int ks = 0; ks < 2; ks++) {
                    int row = wr * 32 + mf * 16 + (lane & 15);
                    int c16 = ks * 2 + (lane >> 4);
                    ldsm_x4(ah[mf][ks], PLG(s, 0) + SW64(row, c16));
                }
#pragma unroll
            for (int nfp = 0; nfp < 4; nfp++) {
#pragma unroll
                for (int ks = 0; ks < 2; ks++) {
                    uint32_t b4[4];
                    int row = wc * 64 + nfp * 16 + (lane & 15);
                    int c16 = ks * 2 + (lane >> 4);
                    ldsm_x4(b4, PLG(s, 1) + SW64(row, c16));
#pragma unroll
                    for (int mf = 0; mf < 2; mf++) {
                        mma_bf16b(c[mf][2 * nfp],     ah[mf][ks], b4[0], b4[2]);
                        mma_bf16b(c[mf][2 * nfp + 1], ah[mf][ks], b4[1], b4[3]);
                    }
                }
            }
        }
    }

#pragma unroll
    for (int mf = 0; mf < 2; mf++)
#pragma unroll
        for (int nf = 0; nf < 8; nf++) {
            int lcol = wc * 64 + nf * 8 + 2 * tig;
            int r0 = bm * 128 + wr * 32 + mf * 16 + g;
            float v0 = c[mf][nf][0] + sbias[lcol];
            float v1 = c[mf][nf][1] + sbias[lcol + 1];
            float v2 = c[mf][nf][2] + sbias[lcol];
            float v3 = c[mf][nf][3] + sbias[lcol + 1];
            if (isloc) {
                int fc = bn * 128 + lcol;
                g_Pf[(size_t)r0 * LC + fc]           = v0;
                g_Pf[(size_t)r0 * LC + fc + 1]       = v1;
                g_Pf[(size_t)(r0 + 8) * LC + fc]     = v2;
                g_Pf[(size_t)(r0 + 8) * LC + fc + 1] = v3;
            } else {
                int gcol = bn * 128 + lcol;
                *(uint32_t*)&g_Pg[(size_t)r0 * GC + gcol]       = pack_bf16(v0, v1);
                *(uint32_t*)&g_Pg[(size_t)(r0 + 8) * GC + gcol] = pack_bf16(v2, v3);
            }
        }
}

// ---------------- merged: M partials [0,128) | prep_local [128,2176) ----------------
__global__ __launch_bounds__(256) void mpart_prep() {
    __shared__ float Ls[64 * 68];
    const int bx = blockIdx.x;
    const int tid = threadIdx.x;
    if (bx < 128) {
        const int bh = bx & 15, b = bh >> 3, h = bh & 7;
        const int part = bx >> 4;
        const int e = tid & 63, d0 = tid >> 6;
        float acc[16];
#pragma unroll
        for (int i = 0; i < 16; i++) acc[i] = 0.f;
        const int colbase = 512 + h * 64;
        for (int t = 0; t < 4; t++) {
            const int s0 = (part * 4 + t) * 64;
            __syncthreads();
#pragma unroll
            for (int ch = 0; ch < 4; ch++) {
                int idx = tid + 256 * ch;
                int r = idx >> 4, c4 = (idx & 15) * 4;
                *(float4*)&Ls[r * 68 + c4] =
                    *(const float4*)&g_Pf[(size_t)(b * SEQ + s0 + r) * LC + colbase + c4];
            }
            __syncthreads();
            for (int r = 0; r < 64; r++) {
                float le = Ls[r * 68 + e];
#pragma unroll
                for (int i = 0; i < 16; i++)
                    acc[i] += Ls[r * 68 + d0 + 4 * i] * le;
            }
        }
#pragma unroll
        for (int i = 0; i < 16; i++)
            g_Mpart[((size_t)part * 16 + bh) * 4096 + (d0 + 4 * i) * 64 + e] = acc[i];
    } else {
        int t = (bx - 128) * 256 + tid;
        int r = t >> 7, c4 = (t & 127) * 4;
        size_t grow = (size_t)r * LC;
        size_t po = (size_t)r * 512 + c4;
        float4 k = *(const float4*)&g_Pf[grow + 1024 + c4];
        __nv_bfloat162 h01, h23, l01, l23;
        split2(k.x, h01.x, l01.x); split2(k.y, h01.y, l01.y);
        split2(k.z, h23.x, l23.x); split2(k.w, h23.y, l23.y);
        *(__nv_bfloat162*)&g_K2h[po]     = h01;
        *(__nv_bfloat162*)&g_K2h[po + 2] = h23;
        *(__nv_bfloat162*)&g_K2l[po]     = l01;
        *(__nv_bfloat162*)&g_K2l[po + 2] = l23;
        float4 v1 = *(const float4*)&g_Pf[grow + 1536 + c4];
        split2(v1.x, h01.x, l01.x); split2(v1.y, h01.y, l01.y);
        split2(v1.z, h23.x, l23.x); split2(v1.w, h23.y, l23.y);
        *(__nv_bfloat162*)&g_Vmh[po]     = h01;
        *(__nv_bfloat162*)&g_Vmh[po + 2] = h23;
        *(__nv_bfloat162*)&g_Vml[po]     = l01;
        *(__nv_bfloat162*)&g_Vml[po + 2] = l23;
    }
}

__global__ __launch_bounds__(256) void reduce_M() {
    const int t = blockIdx.x * 256 + threadIdx.x;
    const int bh = t >> 12, idx = t & 4095;
    float s = 0.f;
#pragma unroll
    for (int p = 0; p < 8; p++) s += g_Mpart[((size_t)p * 16 + bh) * 4096 + idx];
    g_M[(size_t)bh * 4096 + idx] = s;
}

// ---------------- LQ' = LQ @ M (fp32, in place) ----------------
__global__ __launch_bounds__(256) void lq_update() {
    __shared__ float Ms[64 * 65];
    __shared__ float Ls[64 * 68];
    const int rb = blockIdx.x, h = blockIdx.y;
    const int row0 = rb * 64, b = row0 >> 11, bh = b * 8 + h;
    const int tid = threadIdx.x;
    const int colbase = h * 64;
#pragma unroll
    for (int ch = 0; ch < 16; ch++) {
        int idx = tid + 256 * ch;
        Ms[(idx >> 6) * 65 + (idx & 63)] = g_M[(size_t)bh * 4096 + idx];
    }
#pragma unroll
    for (int ch = 0; ch < 4; ch++) {
        int idx = tid + 256 * ch;
        int r = idx >> 4, c4 = (idx & 15) * 4;
        *(float4*)&Ls[r * 68 + c4] =
            *(const float4*)&g_Pf[(size_t)(row0 + r) * LC + colbase + c4];
    }
    __syncthreads();
    const int e = tid & 63, r0 = tid >> 6;
    float acc[16];
#pragma unroll
    for (int i = 0; i < 16; i++) acc[i] = 0.f;
    for (int d = 0; d < 64; d++) {
        float mv = Ms[d * 65 + e];
#pragma unroll
        for (int i = 0; i < 16; i++)
            acc[i] += Ls[(r0 + 4 * i) * 68 + d] * mv;
    }
#pragma unroll
    for (int i = 0; i < 16; i++)
        g_Pf[(size_t)(row0 + r0 + 4 * i) * LC + colbase + e] = acc[i];
}

// ---------------- merged flash: [0,256) local, [256,512) global ----------------
__global__ __launch_bounds__(256, 2) void flash_all(const float* __restrict__ mask,
                                                    float* __restrict__ out) {
    extern __shared__ char fsm[];
    const int tid = threadIdx.x, lane = tid & 31, warp = tid >> 5;
    const int g = lane >> 2, tig = lane & 3;
    const int bx = blockIdx.x;
    const int lr = tid >> 2, lch = tid & 3;

    if (bx < 256) {
#define LF_KH(s) ((__nv_bfloat16*)(fsm + (s) * 36864))
#define LF_KL(s) ((__nv_bfloat16*)(fsm + (s) * 36864 + 9216))
#define LF_VH(s) ((__nv_bfloat16*)(fsm + (s) * 36864 + 18432))
#define LF_VL(s) ((__nv_bfloat16*)(fsm + (s) * 36864 + 27648))
        const int qb = bx & 15, by = bx >> 4;
        const int b = by >> 3, h = by & 7;
        const int rowbase = b * SEQ;

#define LF_ISS(kt, s) {                                                        \
        size_t go = (size_t)(rowbase + (kt) * 64 + lr) * 512 + h * 64 + lch * 16; \
        cp16(LF_KH(s) + lr * 72 + lch * 16,     &g_K2h[go]);                   \
        cp16(LF_KH(s) + lr * 72 + lch * 16 + 8, &g_K2h[go + 8]);               \
        cp16(LF_KL(s) + lr * 72 + lch * 16,     &g_K2l[go]);                   \
        cp16(LF_KL(s) + lr * 72 + lch * 16 + 8, &g_K2l[go + 8]);               \
        cp16(LF_VH(s) + lr * 72 + lch * 16,     &g_Vmh[go]);                   \
        cp16(LF_VH(s) + lr * 72 + lch * 16 + 8, &g_Vmh[go + 8]);               \
        cp16(LF_VL(s) + lr * 72 + lch * 16,     &g_Vml[go]);                   \
        cp16(LF_VL(s) + lr * 72 + lch * 16 + 8, &g_Vml[go + 8]); }

        uint32_t qh[4][4], ql[4][4];
        const int qr0 = rowbase + qb * 128 + warp * 16 + g;
        const float* P0 = &g_Pf[(size_t)qr0 * LC + h * 64];
        const float* P1 = &g_Pf[(size_t)(qr0 + 8) * LC + h * 64];
#pragma unroll
        for (int ks = 0; ks < 4; ks++) {
            int c0 = ks * 16 + 2 * tig;
            pack_hl(P0[c0],     P0[c0 + 1], qh[ks][0], ql[ks][0]);
            pack_hl(P1[c0],     P1[c0 + 1], qh[ks][1], ql[ks][1]);
            pack_hl(P0[c0 + 8], P0[c0 + 9], qh[ks][2], ql[ks][2]);
            pack_hl(P1[c0 + 8], P1[c0 + 9], qh[ks][3], ql[ks][3]);
        }

        LF_ISS(0, 0); asm volatile("cp.async.commit_group;");

        float of[8][4];
#pragma unroll
        for (int nf = 0; nf < 8; nf++)
#pragma unroll
            for (int i = 0; i < 4; i++) of[nf][i] = 0.f;
        float m0 = -1e30f, m1 = -1e30f, l0 = 0.f, l1 = 0.f;

        for (int kt = 0; kt < 32; kt++) {
            const int s = kt & 1;
            if (kt + 1 < 32) { LF_ISS(kt + 1, s ^ 1); }
            asm volatile("cp.async.commit_group;");
            asm volatile("cp.async.wait_group 1;");
            __syncthreads();

            __nv_bfloat16* Kh = LF_KH(s);
            __nv_bfloat16* Kl = LF_KL(s);
            __nv_bfloat16* Vh = LF_VH(s);
            __nv_bfloat16* Vl = LF_VL(s);

            float sf[8][4];
#pragma unroll
            for (int nfp = 0; nfp < 4; nfp++) {
#pragma unroll
                for (int i = 0; i < 4; i++) { sf[2*nfp][i] = 0.f; sf[2*nfp+1][i] = 0.f; }
#pragma unroll
                for (int ks = 0; ks < 4; ks++) {
                    uint32_t kh4[4], kl4[4];
                    int row = nfp * 16 + (lane & 15);
                    int col = ks * 16 + (lane >> 4) * 8;
                    ldsm_x4(kh4, cvta_s(&Kh[row * 72 + col]));
                    ldsm_x4(kl4, cvta_s(&Kl[row * 72 + col]));
                    mma_bf16b(sf[2 * nfp],     qh[ks], kh4[0], kh4[2]);
                    mma_bf16b(sf[2 * nfp],     ql[ks], kh4[0], kh4[2]);
                    mma_bf16b(sf[2 * nfp],     qh[ks], kl4[0], kl4[2]);
                    mma_bf16b(sf[2 * nfp + 1], qh[ks], kh4[1], kh4[3]);
                    mma_bf16b(sf[2 * nfp + 1], ql[ks], kh4[1], kh4[3]);
                    mma_bf16b(sf[2 * nfp + 1], qh[ks], kl4[1], kl4[3]);
                }
            }

            float mx0 = -1e30f, mx1 = -1e30f;
#pragma unroll
            for (int nf = 0; nf < 8; nf++) {
                sf[nf][0] *= 0.125f; sf[nf][1] *= 0.125f;
                sf[nf][2] *= 0.125f; sf[nf][3] *= 0.125f;
                mx0 = fmaxf(mx0, fmaxf(sf[nf][0], sf[nf][1]));
                mx1 = fmaxf(mx1, fmaxf(sf[nf][2], sf[nf][3]));
            }
            mx0 = fmaxf(mx0, __shfl_xor_sync(~0u, mx0, 1));
            mx0 = fmaxf(mx0, __shfl_xor_sync(~0u, mx0, 2));
            mx1 = fmaxf(mx1, __shfl_xor_sync(~0u, mx1, 1));
            mx1 = fmaxf(mx1, __shfl_xor_sync(~0u, mx1, 2));
            float mn0 = fmaxf(m0, mx0), mn1 = fmaxf(m1, mx1);
            float cr0 = __expf(m0 - mn0), cr1 = __expf(m1 - mn1);
            m0 = mn0; m1 = mn1;

            float ps0 = 0.f, ps1 = 0.f;
            uint32_t pah[4][4];
#pragma unroll
            for (int nf = 0; nf < 8; nf++) {
                float p0 = __expf(sf[nf][0] - mn0), p1 = __expf(sf[nf][1] - mn0);
                float p2 = __expf(sf[nf][2] - mn1), p3 = __expf(sf[nf][3] - mn1);
                ps0 += p0 + p1; ps1 += p2 + p3;
                int ks = nf >> 1;
                if (nf & 1) { pah[ks][2] = pack_bf16(p0, p1); pah[ks][3] = pack_bf16(p2, p3); }
                else        { pah[ks][0] = pack_bf16(p0, p1); pah[ks][1] = pack_bf16(p2, p3); }
            }
            ps0 += __shfl_xor_sync(~0u, ps0, 1); ps0 += __shfl_xor_sync(~0u, ps0, 2);
            ps1 += __shfl_xor_sync(~0u, ps1, 1); ps1 += __shfl_xor_sync(~0u, ps1, 2);
            l0 = l0 * cr0 + ps0; l1 = l1 * cr1 + ps1;
#pragma unroll
            for (int nf = 0; nf < 8; nf++) {
                of[nf][0] *= cr0; of[nf][1] *= cr0; of[nf][2] *= cr1; of[nf][3] *= cr1;
            }
#pragma unroll
            for (int nfp = 0; nfp < 4; nfp++)
#pragma unroll
                for (int ks = 0; ks < 4; ks++) {
                    uint32_t vh4[4], vl4[4];
                    int row = ks * 16 + (lane & 15);
                    int col = nfp * 16 + (lane >> 4) * 8;
                    ldsm_x4t(vh4, cvta_s(&Vh[row * 72 + col]));
                    ldsm_x4t(vl4, cvta_s(&Vl[row * 72 + col]));
                    mma_bf16b(of[2 * nfp],     pah[ks], vh4[0], vh4[1]);
                    mma_bf16b(of[2 * nfp],     pah[ks], vl4[0], vl4[1]);
                    mma_bf16b(of[2 * nfp + 1], pah[ks], vh4[2], vh4[3]);
                    mma_bf16b(of[2 * nfp + 1], pah[ks], vl4[2], vl4[3]);
                }
            __syncthreads();
        }

        const float inv0 = 1.f / l0, inv1 = 1.f / l1;
        const int r0 = rowbase + qb * 128 + warp * 16 + g;
#pragma unroll
        for (int nf = 0; nf < 8; nf++) {
            int col = (8 + h) * 64 + nf * 8 + 2 * tig;
            out[(size_t)r0 * HID + col]           = of[nf][0] * inv0;
            out[(size_t)r0 * HID + col + 1]       = of[nf][1] * inv0;
            out[(size_t)(r0 + 8) * HID + col]     = of[nf][2] * inv1;
            out[(size_t)(r0 + 8) * HID + col + 1] = of[nf][3] * inv1;
        }
    } else {
        __nv_bfloat16* Qs = (__nv_bfloat16*)fsm;
        float* maskS = (float*)(fsm + 18432);
#define GF_K(s) ((__nv_bfloat16*)(fsm + 26624 + (s) * 18432))
#define GF_V(s) ((__nv_bfloat16*)(fsm + 26624 + (s) * 18432 + 9216))
        const int y = bx - 256;
        const int qb = y & 15, by = y >> 4;
        const int b = by >> 3, h = by & 7;
        const int qcol = h * 64, kcol = 512 + h * 64, vcol = 1024 + h * 64;
        const int rowbase = b * SEQ;

#define GF_ISS(kt, s) {                                                        \
        size_t grow = (size_t)(rowbase + (kt) * 64 + lr) * GC;                 \
        cp16(GF_K(s) + lr * 72 + lch * 16,     &g_Pg[grow + kcol + lch * 16]); \
        cp16(GF_K(s) + lr * 72 + lch * 16 + 8, &g_Pg[grow + kcol + lch * 16 + 8]); \
        cp16(GF_V(s) + lr * 72 + lch * 16,     &g_Pg[grow + vcol + lch * 16]); \
        cp16(GF_V(s) + lr * 72 + lch * 16 + 8, &g_Pg[grow + vcol + lch * 16 + 8]); }

#pragma unroll
        for (int i = 0; i < 8; i++) maskS[tid + 256 * i] = mask[b * SEQ + tid + 256 * i];
#pragma unroll
        for (int i = 0; i < 4; i++) {
            int idx = tid + 256 * i;
            int r = idx >> 3, ch = idx & 7;
            *(uint4*)&Qs[r * 72 + ch * 8] =
                *(const uint4*)&g_Pg[(size_t)(rowbase + qb * 128 + r) * GC + qcol + ch * 8];
        }
        GF_ISS(0, 0); asm volatile("cp.async.commit_group;");
        GF_ISS(1, 1); asm volatile("cp.async.commit_group;");
        __syncthreads();

        uint32_t qf[4][4];
#pragma unroll
        for (int ks = 0; ks < 4; ks++) {
            int row = warp * 16 + (lane & 15);
            int col = ks * 16 + (lane >> 4) * 8;
            ldsm_x4(qf[ks], cvta_s(&Qs[row * 72 + col]));
        }

        float of[8][4];
#pragma unroll
        for (int nf = 0; nf < 8; nf++)
#pragma unroll
            for (int i = 0; i < 4; i++) of[nf][i] = 0.f;
        float m0 = -1e30f, m1 = -1e30f, l0 = 0.f, l1 = 0.f;

        for (int kt = 0; kt < 32; kt++) {
            const int s = kt % 3;
            asm volatile("cp.async.wait_group 1;");
            __syncthreads();
            if (kt + 2 < 32) { GF_ISS(kt + 2, (kt + 2) % 3); }
            asm volatile("cp.async.commit_group;");

            __nv_bfloat16* Ks = GF_K(s);
            __nv_bfloat16* Vs = GF_V(s);

            float sf[8][4];
#pragma unroll
            for (int nfp = 0; nfp < 4; nfp++) {
#pragma unroll
                for (int i = 0; i < 4; i++) { sf[2*nfp][i] = 0.f; sf[2*nfp+1][i] = 0.f; }
#pragma unroll
                for (int ks = 0; ks < 4; ks++) {
                    uint32_t k4[4];
                    int row = nfp * 16 + (lane & 15);
                    int col = ks * 16 + (lane >> 4) * 8;
                    ldsm_x4(k4, cvta_s(&Ks[row * 72 + col]));
                    mma_bf16b(sf[2 * nfp],     qf[ks], k4[0], k4[2]);
                    mma_bf16b(sf[2 * nfp + 1], qf[ks], k4[1], k4[3]);
                }
            }

            float mx0 = -1e30f, mx1 = -1e30f;
#pragma unroll
            for (int nf = 0; nf < 8; nf++) {
                float a0 = maskS[kt * 64 + nf * 8 + 2 * tig];
                float a1 = maskS[kt * 64 + nf * 8 + 2 * tig + 1];
                sf[nf][0] = sf[nf][0] * 0.125f + a0;
                sf[nf][1] = sf[nf][1] * 0.125f + a1;
                sf[nf][2] = sf[nf][2] * 0.125f + a0;
                sf[nf][3] = sf[nf][3] * 0.125f + a1;
                mx0 = fmaxf(mx0, fmaxf(sf[nf][0], sf[nf][1]));
                mx1 = fmaxf(mx1, fmaxf(sf[nf][2], sf[nf][3]));
            }
            mx0 = fmaxf(mx0, __shfl_xor_sync(~0u, mx0, 1));
            mx0 = fmaxf(mx0, __shfl_xor_sync(~0u, mx0, 2));
            mx1 = fmaxf(mx1, __shfl_xor_sync(~0u, mx1, 1));
            mx1 = fmaxf(mx1, __shfl_xor_sync(~0u, mx1, 2));
            float mn0 = fmaxf(m0, mx0), mn1 = fmaxf(m1, mx1);
            float cr0 = __expf(m0 - mn0), cr1 = __expf(m1 - mn1);
            m0 = mn0; m1 = mn1;

            float ps0 = 0.f, ps1 = 0.f;
            uint32_t pa[4][4];
#pragma unroll
            for (int nf = 0; nf < 8; nf++) {
                float p0 = __expf(sf[nf][0] - mn0), p1 = __expf(sf[nf][1] - mn0);
                float p2 = __expf(sf[nf][2] - mn1), p3 = __expf(sf[nf][3] - mn1);
                ps0 += p0 + p1; ps1 += p2 + p3;
                int ks = nf >> 1;
                if (nf & 1) { pa[ks][2] = pack_bf16(p0, p1); pa[ks][3] = pack_bf16(p2, p3); }
                else        { pa[ks][0] = pack_bf16(p0, p1); pa[ks][1] = pack_bf16(p2, p3); }
            }
            ps0 += __shfl_xor_sync(~0u, ps0, 1); ps0 += __shfl_xor_sync(~0u, ps0, 2);
            ps1 += __shfl_xor_sync(~0u, ps1, 1); ps1 += __shfl_xor_sync(~0u, ps1, 2);
            l0 = l0 * cr0 + ps0; l1 = l1 * cr1 + ps1;
#pragma unroll
            for (int nf = 0; nf < 8; nf++) {
                of[nf][0] *= cr0; of[nf][1] *= cr0; of[nf][2] *= cr1; of[nf][3] *= cr1;
            }
#pragma unroll
            for (int nfp = 0; nfp < 4; nfp++)
#pragma unroll
                for (int ks = 0; ks < 4; ks++) {
                    uint32_t v4[4];
                    int row = ks * 16 + (lane & 15);
                    int col = nfp * 16 + (lane >> 4) * 8;
                    ldsm_x4t(v4, cvta_s(&Vs[row * 72 + col]));
                    mma_bf16b(of[2 * nfp],     pa[ks], v4[0], v4[1]);
                    mma_bf16b(of[2 * nfp + 1], pa[ks], v4[2], v4[3]);
                }
        }

        const float inv0 = 1.f / l0, inv1 = 1.f / l1;
        const int r0 = rowbase + qb * 128 + warp * 16 + g;
#pragma unroll
        for (int nf = 0; nf < 8; nf++) {
            int col = h * 64 + nf * 8 + 2 * tig;
            out[(size_t)r0 * HID + col]           = of[nf][0] * inv0;
            out[(size_t)r0 * HID + col + 1]       = of[nf][1] * inv0;
            out[(size_t)(r0 + 8) * HID + col]     = of[nf][2] * inv1;
            out[(size_t)(r0 + 8) * HID + col + 1] = of[nf][3] * inv1;
        }
    }
}

// ---------------------------------------------------------------------------
extern "C" void kernel_launch(void* const* d_in, const int* in_sizes, int n_in,
                              void* d_out, int out_size) {
    (void)in_sizes; (void)n_in; (void)out_size;
    const float* X    = (const float*)d_in[0];
    const float* mask = (const float*)d_in[1];
    ProjArgs pa;
    for (int i = 0; i < 8; i++) {
        pa.w[i] = (const float*)d_in[2 + 2 * i];
        pa.b[i] = (const float*)d_in[3 + 2 * i];
    }
    float* out = (float*)d_out;

    const int PASMEM = 1024 + 3 * 32768;    // 99328
    const int FASMEM = 81920;               // flash_all union (GF 81920, LF 73728)
    cudaFuncSetAttribute(proj_all, cudaFuncAttributeMaxDynamicSharedMemorySize, PASMEM);
    cudaFuncSetAttribute(flash_all, cudaFuncAttributeMaxDynamicSharedMemorySize, FASMEM);

    prep_all<<<7694, 256>>>(X, pa);
    proj_all<<<896, 256, PASMEM>>>();
    mpart_prep<<<2176, 256>>>();
    reduce_M<<<256, 256>>>();
    lq_update<<<dim3(64, 8), 256>>>();
    flash_all<<<512, 256, FASMEM>>>(mask, out);
}